// round 4
// baseline (speedup 1.0000x reference)
#include <cuda_runtime.h>
#include <cuda_fp16.h>
#include <cuda_fp8.h>
#include <cstdint>

#define DM 2048   // d_model
#define BATCH 2048
#define NT 64     // num transforms
#define RK 32     // rank

// ---------------------------------------------------------------------------
// Static device scratch. Each fp32 tensor is split  x = h + l:
//   h = fp16(x)  (stored as fp16 for the hh pass, and as e4m3 for cross passes)
//   l = (x - h) * 2^11 stored as e4m3 (cross passes), combined with 2^-11.
// ---------------------------------------------------------------------------
__device__ __half        g_x16[BATCH * DM];
__device__ unsigned char g_x8h[BATCH * DM], g_x8l[BATCH * DM];
__device__ __half        g_v16[DM * DM];
__device__ unsigned char g_v8h[DM * DM], g_v8l[DM * DM];
__device__ __half        g_w16[DM * DM];                       // Wt = U^T  [d][k]
__device__ unsigned char g_w8h[DM * DM], g_w8l[DM * DM];
__device__ __half        g_gv16[BATCH * DM];                   // gated Vx  [b][k]
__device__ unsigned char g_gv8h[BATCH * DM], g_gv8l[BATCH * DM];
__device__ float g_vpart[4096];    // per-block sum-of-squares partials (V)
__device__ float g_upart[1024];    // per-block partials (U): [n*16 + dblock]

// ---------------------------------------------------------------------------
// PTX helpers (portable sm_80/sm_89 subset; no tcgen05 — ptxas targets sm_103)
// ---------------------------------------------------------------------------
__device__ __forceinline__ uint32_t smem_u32(const void* p) {
    return (uint32_t)__cvta_generic_to_shared(p);
}
__device__ __forceinline__ void cp16(uint32_t dst, const void* src) {
    asm volatile("cp.async.cg.shared.global [%0], [%1], 16;\n" :: "r"(dst), "l"(src));
}
__device__ __forceinline__ void cp_commit() {
    asm volatile("cp.async.commit_group;\n" ::: "memory");
}
template<int N>
__device__ __forceinline__ void cp_wait() {
    asm volatile("cp.async.wait_group %0;\n" :: "n"(N) : "memory");
}
__device__ __forceinline__ void ldsm4(uint32_t* r, uint32_t addr) {
    asm volatile("ldmatrix.sync.aligned.m8n8.x4.shared.b16 {%0,%1,%2,%3}, [%4];"
                 : "=r"(r[0]), "=r"(r[1]), "=r"(r[2]), "=r"(r[3]) : "r"(addr));
}
__device__ __forceinline__ void mma_f16(float* d, const uint32_t* a, const uint32_t* b) {
    asm volatile(
        "mma.sync.aligned.m16n8k16.row.col.f32.f16.f16.f32 "
        "{%0,%1,%2,%3}, {%4,%5,%6,%7}, {%8,%9}, {%0,%1,%2,%3};"
        : "+f"(d[0]), "+f"(d[1]), "+f"(d[2]), "+f"(d[3])
        : "r"(a[0]), "r"(a[1]), "r"(a[2]), "r"(a[3]), "r"(b[0]), "r"(b[1]));
}
__device__ __forceinline__ void mma_e4m3(float* d, const uint32_t* a, const uint32_t* b) {
    asm volatile(
        "mma.sync.aligned.m16n8k32.row.col.f32.e4m3.e4m3.f32 "
        "{%0,%1,%2,%3}, {%4,%5,%6,%7}, {%8,%9}, {%0,%1,%2,%3};"
        : "+f"(d[0]), "+f"(d[1]), "+f"(d[2]), "+f"(d[3])
        : "r"(a[0]), "r"(a[1]), "r"(a[2]), "r"(a[3]), "r"(b[0]), "r"(b[1]));
}
// pack two floats to e4m3x2, lo -> low byte
__device__ __forceinline__ unsigned short f8pack2(float lo, float hi) {
    unsigned short r;
    asm("{\n\t.reg .b16 t;\n\tcvt.rn.satfinite.e4m3x2.f32 t, %2, %1;\n\t"
        "mov.b16 %0, t;\n\t}" : "=h"(r) : "f"(lo), "f"(hi));
    return r;
}

// split float4 -> fp16x4 bits + e4m3x4(h) + e4m3x4(l*2048)
__device__ __forceinline__ void split4(const float4 v, uint32_t& h16a, uint32_t& h16b,
                                       uint32_t& h8, uint32_t& l8)
{
    __half2 a = __floats2half2_rn(v.x, v.y);
    __half2 b = __floats2half2_rn(v.z, v.w);
    h16a = *(const uint32_t*)&a;
    h16b = *(const uint32_t*)&b;
    float h0 = __low2float(a), h1 = __high2float(a);
    float h2 = __low2float(b), h3 = __high2float(b);
    unsigned short p01 = f8pack2(h0, h1), p23 = f8pack2(h2, h3);
    h8 = (uint32_t)p01 | ((uint32_t)p23 << 16);
    unsigned short q01 = f8pack2((v.x - h0) * 2048.f, (v.y - h1) * 2048.f);
    unsigned short q23 = f8pack2((v.z - h2) * 2048.f, (v.w - h3) * 2048.f);
    l8 = (uint32_t)q01 | ((uint32_t)q23 << 16);
}

// ---------------------------------------------------------------------------
// Prep: x -> splits (no norms needed)
// ---------------------------------------------------------------------------
__global__ __launch_bounds__(256) void prep_x(const float4* __restrict__ src)
{
    int i = blockIdx.x * 256 + threadIdx.x;
    uint32_t h16a, h16b, h8, l8;
    split4(src[i], h16a, h16b, h8, l8);
    ((uint2*)g_x16)[i] = make_uint2(h16a, h16b);
    ((uint32_t*)g_x8h)[i] = h8;
    ((uint32_t*)g_x8l)[i] = l8;
}

// Prep: V -> splits + per-block sum-of-squares partials (64 blocks / transform)
__global__ __launch_bounds__(256) void prep_v(const float4* __restrict__ src)
{
    int i = blockIdx.x * 256 + threadIdx.x;
    float4 v = src[i];
    uint32_t h16a, h16b, h8, l8;
    split4(v, h16a, h16b, h8, l8);
    ((uint2*)g_v16)[i] = make_uint2(h16a, h16b);
    ((uint32_t*)g_v8h)[i] = h8;
    ((uint32_t*)g_v8l)[i] = l8;

    float s = v.x*v.x + v.y*v.y + v.z*v.z + v.w*v.w;
    __shared__ float red[256];
    red[threadIdx.x] = s;
    __syncthreads();
    for (int off = 128; off > 0; off >>= 1) {
        if (threadIdx.x < off) red[threadIdx.x] += red[threadIdx.x + off];
        __syncthreads();
    }
    if (threadIdx.x == 0) g_vpart[blockIdx.x] = red[0];
}

// Prep: U (64,2048,32) -> Wt[d][k] splits + per-(n,dblock) partials
__global__ __launch_bounds__(256) void prep_u(const float* __restrict__ Uw)
{
    const int n  = blockIdx.x;        // 0..63
    const int d0 = blockIdx.y * 128;  // 16 blocks
    float ss = 0.0f;
    #pragma unroll
    for (int it = 0; it < 4; it++) {
        int lin = threadIdx.x + it * 256;   // 0..1023
        int dl = lin >> 3;                  // 0..127
        int q  = lin & 7;                   // float4 chunk of r
        float4 v = *(const float4*)(Uw + ((size_t)n * DM + d0 + dl) * RK + q * 4);
        uint32_t h16a, h16b, h8, l8;
        split4(v, h16a, h16b, h8, l8);
        size_t o = (size_t)(d0 + dl) * DM + n * RK + q * 4;
        *(uint2*)(g_w16 + o) = make_uint2(h16a, h16b);
        *(uint32_t*)(g_w8h + o) = h8;
        *(uint32_t*)(g_w8l + o) = l8;
        ss += v.x*v.x + v.y*v.y + v.z*v.z + v.w*v.w;
    }
    __shared__ float red[256];
    red[threadIdx.x] = ss;
    __syncthreads();
    for (int off = 128; off > 0; off >>= 1) {
        if (threadIdx.x < off) red[threadIdx.x] += red[threadIdx.x + off];
        __syncthreads();
    }
    if (threadIdx.x == 0) g_upart[blockIdx.x * 16 + blockIdx.y] = red[0];
}

__global__ void frob_kernel(float* __restrict__ frob)
{
    int n = threadIdx.x;  // 64 threads
    float su = 0.0f, sv = 0.0f;
    #pragma unroll
    for (int j = 0; j < 16; j++) su += g_upart[n * 16 + j];
    #pragma unroll
    for (int j = 0; j < 64; j++) sv += g_vpart[n * 64 + j];
    frob[n] = sqrtf(su) * sqrtf(sv) * (1.0f / 256.0f);  // /sqrt(2048*32)
}

// ---------------------------------------------------------------------------
// Gate kernel (fp32, exact): BM=16 -> grid 128 for better chip fill
// ---------------------------------------------------------------------------
__global__ __launch_bounds__(256) void gate_kernel(
    const float* __restrict__ x, const float* __restrict__ enc,
    const float* __restrict__ bias, float* __restrict__ gate)
{
    __shared__ __align__(16) float As[32][20];   // [k][row16]
    __shared__ __align__(16) float Es[32][68];   // [k][n64]

    const int tid = threadIdx.x;
    const int tx = tid & 15, ty = tid >> 4;      // tx: n group, ty: row
    const int b0 = blockIdx.x * 16;
    const int f4 = tid & 7;

    float acc[4] = {0.f, 0.f, 0.f, 0.f};

    for (int d0 = 0; d0 < DM; d0 += 32) {
        if (tid < 128) {
            int lrow = tid >> 3;   // 0..15
            float4 v = *(const float4*)(x + (size_t)(b0 + lrow) * DM + d0 + f4 * 4);
            As[f4*4+0][lrow] = v.x; As[f4*4+1][lrow] = v.y;
            As[f4*4+2][lrow] = v.z; As[f4*4+3][lrow] = v.w;
        }
        #pragma unroll
        for (int p = 0; p < 2; p++) {
            int row = p * 32 + (tid >> 3);
            float4 v = *(const float4*)(enc + (size_t)row * DM + d0 + f4 * 4);
            Es[f4*4+0][row] = v.x; Es[f4*4+1][row] = v.y;
            Es[f4*4+2][row] = v.z; Es[f4*4+3][row] = v.w;
        }
        __syncthreads();
        #pragma unroll
        for (int kk = 0; kk < 32; kk++) {
            float a = As[kk][ty];
            float4 e = *(const float4*)&Es[kk][tx*4];
            acc[0] += a * e.x; acc[1] += a * e.y;
            acc[2] += a * e.z; acc[3] += a * e.w;
        }
        __syncthreads();
    }
    int b = b0 + ty;
    #pragma unroll
    for (int j = 0; j < 4; j++) {
        int n = tx*4 + j;
        float p = acc[j] - bias[n];
        gate[b * NT + n] = (p > 0.0f) ? p : 0.0f;
    }
}

// ---------------------------------------------------------------------------
// GEMM: D[m,n] = sum_k A[m,k]*B[n,k], hi(fp16) x hi  +  2^-11 * fp8 cross terms.
// BM=BN=128, BK=32, 8 warps (4m x 2n), warp tile 32x64, 4-stage cp.async.
// Stage (32KB): A16 0 | B16 8K | A8h 16K | A8l 20K | B8h 24K | B8l 28K
// MODE 0: A=x, B=Vflat; epilogue *gate -> GVx splits
// MODE 1: A=GVx, B=Wt;  epilogue fp32 -> out
// ---------------------------------------------------------------------------
#define MMA_SMEM 131072
#define STG 32768u

template<int MODE>
__global__ __launch_bounds__(256, 1) void mma_gemm(const float* __restrict__ gate,
                                                   float* __restrict__ outf)
{
    extern __shared__ char sm[];
    const uint32_t sbase = smem_u32(sm);

    const int tid  = threadIdx.x;
    const int wid  = tid >> 5;
    const int lane = tid & 31;
    const int n0 = blockIdx.x * 128;
    const int b0 = blockIdx.y * 128;
    const int wm = (wid & 3) * 32;
    const int wn = (wid >> 2) * 64;

    const __half* __restrict__        A16 = (MODE == 0) ? g_x16 : g_gv16;
    const unsigned char* __restrict__ A8h = (MODE == 0) ? g_x8h : g_gv8h;
    const unsigned char* __restrict__ A8l = (MODE == 0) ? g_x8l : g_gv8l;
    const __half* __restrict__        B16 = (MODE == 0) ? g_v16 : g_w16;
    const unsigned char* __restrict__ B8h = (MODE == 0) ? g_v8h : g_w8h;
    const unsigned char* __restrict__ B8l = (MODE == 0) ? g_v8l : g_w8l;

    float acc16[2][8][4], acc8[2][8][4];
    #pragma unroll
    for (int i = 0; i < 2; i++)
        #pragma unroll
        for (int j = 0; j < 8; j++)
            #pragma unroll
            for (int e = 0; e < 4; e++) { acc16[i][j][e] = 0.f; acc8[i][j][e] = 0.f; }

    // ---- cp.async per-thread coords ----
    const int cb16 = (tid & 3) * 16;         // byte col in 64B fp16 row
    const int cb8  = (tid & 1) * 16;         // byte col in 32B fp8 row

    auto issue = [&](int ch) {
        const uint32_t st = sbase + (uint32_t)(ch & 3) * STG;
        const int kb = ch * 32;
        #pragma unroll
        for (int it = 0; it < 2; ++it) {
            int row = it * 64 + (tid >> 2);
            uint32_t sw = (uint32_t)row * 64 + (uint32_t)(cb16 ^ ((row & 6) << 3));
            cp16(st + sw,
                 (const char*)(A16 + (size_t)(b0 + row) * DM + kb) + cb16);
            cp16(st + 8192 + sw,
                 (const char*)(B16 + (size_t)(n0 + row) * DM + kb) + cb16);
        }
        {
            int row = tid >> 1;  // 0..127
            uint32_t sw = (uint32_t)row * 32 + (uint32_t)(cb8 ^ ((row & 4) << 2));
            cp16(st + 16384 + sw, A8h + (size_t)(b0 + row) * DM + kb + cb8);
            cp16(st + 20480 + sw, A8l + (size_t)(b0 + row) * DM + kb + cb8);
            cp16(st + 24576 + sw, B8h + (size_t)(n0 + row) * DM + kb + cb8);
            cp16(st + 28672 + sw, B8l + (size_t)(n0 + row) * DM + kb + cb8);
        }
        cp_commit();
    };

    // ---- ldmatrix lane coords ----
    const int a_row16 = wm + (lane & 15);
    const int a_kc16  = (lane >> 4) * 16;
    const int b_rowb  = wn + (lane & 7) + ((lane >> 4) << 3);
    const int b_kc16  = ((lane >> 3) & 1) * 16;
    const int a_kc8   = (lane >> 4) * 16;
    const int b_kc8   = ((lane >> 3) & 1) * 16;

    issue(0); issue(1); issue(2);

    for (int c = 0; c < 64; ++c) {
        cp_wait<2>();
        __syncthreads();
        if (c + 3 < 64) issue(c + 3);
        else {  // dummy real cp keeps wait_group accounting correct
            cp16(sbase + (uint32_t)((c + 3) & 3) * STG, A8h);
            cp_commit();
        }

        const uint32_t st = sbase + (uint32_t)(c & 3) * STG;

        // ---- fp16 hh pass ----
        #pragma unroll
        for (int k16 = 0; k16 < 2; ++k16) {
            const int koff = k16 * 32;
            uint32_t bh[4][4];
            #pragma unroll
            for (int q = 0; q < 4; ++q) {
                int row = b_rowb + q * 16;
                uint32_t sw = (uint32_t)row * 64 +
                              (uint32_t)((koff + b_kc16) ^ ((row & 6) << 3));
                ldsm4(bh[q], st + 8192 + sw);
            }
            #pragma unroll
            for (int mb = 0; mb < 2; ++mb) {
                int row = a_row16 + mb * 16;
                uint32_t sw = (uint32_t)row * 64 +
                              (uint32_t)((koff + a_kc16) ^ ((row & 6) << 3));
                uint32_t ah[4];
                ldsm4(ah, st + sw);
                #pragma unroll
                for (int q = 0; q < 4; ++q) {
                    mma_f16(acc16[mb][q*2],   ah, &bh[q][0]);
                    mma_f16(acc16[mb][q*2+1], ah, &bh[q][2]);
                }
            }
        }

        // ---- fp8 cross passes (k32) ----
        {
            uint32_t bh8[4][4], bl8[4][4];
            #pragma unroll
            for (int q = 0; q < 4; ++q) {
                int row = b_rowb + q * 16;
                uint32_t sw = (uint32_t)row * 32 +
                              (uint32_t)(b_kc8 ^ ((row & 4) << 2));
                ldsm4(bh8[q], st + 24576 + sw);
                ldsm4(bl8[q], st + 28672 + sw);
            }
            #pragma unroll
            for (int mb = 0; mb < 2; ++mb) {
                int row = a_row16 + mb * 16;
                uint32_t sw = (uint32_t)row * 32 +
                              (uint32_t)(a_kc8 ^ ((row & 4) << 2));
                uint32_t ah8[4], al8[4];
                ldsm4(ah8, st + 16384 + sw);
                ldsm4(al8, st + 20480 + sw);
                #pragma unroll
                for (int q = 0; q < 4; ++q) {
                    mma_e4m3(acc8[mb][q*2],   ah8, &bl8[q][0]);   // h_a * l_b
                    mma_e4m3(acc8[mb][q*2+1], ah8, &bl8[q][2]);
                    mma_e4m3(acc8[mb][q*2],   al8, &bh8[q][0]);   // l_a * h_b
                    mma_e4m3(acc8[mb][q*2+1], al8, &bh8[q][2]);
                }
            }
        }
        __syncthreads();
    }

    // ---- epilogue ----
    const int g = lane >> 2, t = lane & 3;
    const float CS = 1.0f / 2048.0f;
    #pragma unroll
    for (int mb = 0; mb < 2; ++mb) {
        #pragma unroll
        for (int half = 0; half < 2; ++half) {
            const int b = b0 + wm + mb * 16 + g + half * 8;
            #pragma unroll
            for (int ni = 0; ni < 8; ++ni) {
                const int colg = n0 + wn + ni * 8 + t * 2;
                float f0 = acc16[mb][ni][half*2+0] + acc8[mb][ni][half*2+0] * CS;
                float f1 = acc16[mb][ni][half*2+1] + acc8[mb][ni][half*2+1] * CS;
                if (MODE == 0) {
                    const float gv = __ldg(&gate[b * NT + (colg >> 5)]);
                    f0 *= gv; f1 *= gv;
                    __half2 h2 = __floats2half2_rn(f0, f1);
                    float h0 = __low2float(h2), h1 = __high2float(h2);
                    size_t off = (size_t)b * DM + colg;
                    *(uint32_t*)(g_gv16 + off) = *(const uint32_t*)&h2;
                    *(unsigned short*)(g_gv8h + off) = f8pack2(h0, h1);
                    *(unsigned short*)(g_gv8l + off) =
                        f8pack2((f0 - h0) * 2048.f, (f1 - h1) * 2048.f);
                } else {
                    *(float2*)(outf + (size_t)b * DM + colg) = make_float2(f0, f1);
                }
            }
        }
    }
}

// ---------------------------------------------------------------------------
// d_out layout: [output 2048*2048 | gate 2048*64 | frob 64]
// ---------------------------------------------------------------------------
extern "C" void kernel_launch(void* const* d_in, const int* in_sizes, int n_in,
                              void* d_out, int out_size)
{
    const float* x    = (const float*)d_in[0];  // (2048, 2048)
    const float* Vw   = (const float*)d_in[1];  // (64, 32, 2048)
    const float* Uw   = (const float*)d_in[2];  // (64, 2048, 32)
    const float* enc  = (const float*)d_in[3];  // (64, 2048)
    const float* bias = (const float*)d_in[4];  // (64,)

    float* out  = (float*)d_out;
    float* gate = out + BATCH * DM;
    float* frob = gate + BATCH * NT;

    cudaFuncSetAttribute(mma_gemm<0>, cudaFuncAttributeMaxDynamicSharedMemorySize, MMA_SMEM);
    cudaFuncSetAttribute(mma_gemm<1>, cudaFuncAttributeMaxDynamicSharedMemorySize, MMA_SMEM);

    prep_x<<<(BATCH * DM) / 4 / 256, 256>>>((const float4*)x);
    prep_v<<<(DM * DM) / 4 / 256, 256>>>((const float4*)Vw);
    prep_u<<<dim3(NT, DM / 128), 256>>>(Uw);
    gate_kernel<<<BATCH / 16, 256>>>(x, enc, bias, gate);
    frob_kernel<<<1, NT>>>(frob);

    mma_gemm<0><<<dim3(DM / 128, BATCH / 128), 256, MMA_SMEM>>>(gate, nullptr);
    mma_gemm<1><<<dim3(DM / 128, BATCH / 128), 256, MMA_SMEM>>>(nullptr, out);
}

// round 5
// speedup vs baseline: 2.3946x; 2.3946x over previous
#include <cuda_runtime.h>
#include <cuda_fp16.h>
#include <cstdint>

#define DM 2048   // d_model
#define BATCH 2048
#define NT 64     // num transforms
#define RK 32     // rank

// ---------------------------------------------------------------------------
// Static device scratch (no allocation allowed). Single fp16 operand copies.
// ---------------------------------------------------------------------------
__device__ __half g_x16[BATCH * DM];    // x          [b][d]
__device__ __half g_v16[DM * DM];       // V_flat     [k][d]
__device__ __half g_w16[DM * DM];       // Wt = U^T   [d][k]
__device__ __half g_gv16[BATCH * DM];   // gated Vx   [b][k]
__device__ float g_vpart[4096];         // per-block sum-of-squares partials (V)
__device__ float g_upart[1024];         // per-block partials (U): [n*16 + dblk]

// ---------------------------------------------------------------------------
// PTX helpers (portable sm_80 subset; ptxas here targets plain sm_103)
// ---------------------------------------------------------------------------
__device__ __forceinline__ uint32_t smem_u32(const void* p) {
    return (uint32_t)__cvta_generic_to_shared(p);
}
__device__ __forceinline__ void cp16(uint32_t dst, const void* src) {
    asm volatile("cp.async.cg.shared.global [%0], [%1], 16;\n" :: "r"(dst), "l"(src));
}
__device__ __forceinline__ void cp_commit() {
    asm volatile("cp.async.commit_group;\n" ::: "memory");
}
template<int N>
__device__ __forceinline__ void cp_wait() {
    asm volatile("cp.async.wait_group %0;\n" :: "n"(N) : "memory");
}
__device__ __forceinline__ void ldsm4(uint32_t* r, uint32_t addr) {
    asm volatile("ldmatrix.sync.aligned.m8n8.x4.shared.b16 {%0,%1,%2,%3}, [%4];"
                 : "=r"(r[0]), "=r"(r[1]), "=r"(r[2]), "=r"(r[3]) : "r"(addr));
}
__device__ __forceinline__ void mma_f16(float* d, const uint32_t* a, const uint32_t* b) {
    asm volatile(
        "mma.sync.aligned.m16n8k16.row.col.f32.f16.f16.f32 "
        "{%0,%1,%2,%3}, {%4,%5,%6,%7}, {%8,%9}, {%0,%1,%2,%3};"
        : "+f"(d[0]), "+f"(d[1]), "+f"(d[2]), "+f"(d[3])
        : "r"(a[0]), "r"(a[1]), "r"(a[2]), "r"(a[3]), "r"(b[0]), "r"(b[1]));
}

// ---------------------------------------------------------------------------
// Gate kernel (fp32, exact) — R3 version (known good)
// ---------------------------------------------------------------------------
__global__ __launch_bounds__(256) void gate_kernel(
    const float* __restrict__ x, const float* __restrict__ enc,
    const float* __restrict__ bias, float* __restrict__ gate)
{
    __shared__ __align__(16) float As[32][36];
    __shared__ __align__(16) float Es[32][68];

    const int tid = threadIdx.x;
    const int tx = tid & 15, ty = tid >> 4;
    const int b0 = blockIdx.x * 32;
    const int f4 = tid & 7, lrow = tid >> 3;

    float acc[2][4];
    #pragma unroll
    for (int i = 0; i < 2; i++)
        #pragma unroll
        for (int j = 0; j < 4; j++) acc[i][j] = 0.0f;

    for (int d0 = 0; d0 < DM; d0 += 32) {
        {
            float4 v = *(const float4*)(x + (size_t)(b0 + lrow) * DM + d0 + f4 * 4);
            As[f4*4+0][lrow] = v.x; As[f4*4+1][lrow] = v.y;
            As[f4*4+2][lrow] = v.z; As[f4*4+3][lrow] = v.w;
        }
        #pragma unroll
        for (int p = 0; p < 2; p++) {
            int row = p * 32 + lrow;
            float4 v = *(const float4*)(enc + (size_t)row * DM + d0 + f4 * 4);
            Es[f4*4+0][row] = v.x; Es[f4*4+1][row] = v.y;
            Es[f4*4+2][row] = v.z; Es[f4*4+3][row] = v.w;
        }
        __syncthreads();
        #pragma unroll
        for (int kk = 0; kk < 32; kk++) {
            float a0 = As[kk][ty*2 + 0];
            float a1 = As[kk][ty*2 + 1];
            float4 e = *(const float4*)&Es[kk][tx*4];
            acc[0][0] += a0 * e.x; acc[0][1] += a0 * e.y;
            acc[0][2] += a0 * e.z; acc[0][3] += a0 * e.w;
            acc[1][0] += a1 * e.x; acc[1][1] += a1 * e.y;
            acc[1][2] += a1 * e.z; acc[1][3] += a1 * e.w;
        }
        __syncthreads();
    }
    #pragma unroll
    for (int i = 0; i < 2; i++) {
        int b = b0 + ty*2 + i;
        #pragma unroll
        for (int j = 0; j < 4; j++) {
            int n = tx*4 + j;
            float p = acc[i][j] - bias[n];
            gate[b * NT + n] = (p > 0.0f) ? p : 0.0f;
        }
    }
}

// ---------------------------------------------------------------------------
// Prep kernels: fp32 -> fp16, norms fused where the data is already in flight
// ---------------------------------------------------------------------------
__global__ __launch_bounds__(256) void prep_x(const float4* __restrict__ src)
{
    int i = blockIdx.x * 256 + threadIdx.x;
    float4 v = src[i];
    __half2 a = __floats2half2_rn(v.x, v.y);
    __half2 b = __floats2half2_rn(v.z, v.w);
    ((uint2*)g_x16)[i] = make_uint2(*(uint32_t*)&a, *(uint32_t*)&b);
}

__global__ __launch_bounds__(256) void prep_v(const float4* __restrict__ src)
{
    int i = blockIdx.x * 256 + threadIdx.x;
    float4 v = src[i];
    __half2 a = __floats2half2_rn(v.x, v.y);
    __half2 b = __floats2half2_rn(v.z, v.w);
    ((uint2*)g_v16)[i] = make_uint2(*(uint32_t*)&a, *(uint32_t*)&b);

    float s = v.x*v.x + v.y*v.y + v.z*v.z + v.w*v.w;
    __shared__ float red[256];
    red[threadIdx.x] = s;
    __syncthreads();
    for (int off = 128; off > 0; off >>= 1) {
        if (threadIdx.x < off) red[threadIdx.x] += red[threadIdx.x + off];
        __syncthreads();
    }
    if (threadIdx.x == 0) g_vpart[blockIdx.x] = red[0];
}

__global__ __launch_bounds__(256) void prep_u(const float* __restrict__ Uw)
{
    const int n  = blockIdx.x;        // 0..63
    const int d0 = blockIdx.y * 128;  // 16 blocks
    float ss = 0.0f;
    #pragma unroll
    for (int it = 0; it < 4; it++) {
        int lin = threadIdx.x + it * 256;   // 0..1023
        int dl = lin >> 3;                  // 0..127
        int q  = lin & 7;                   // float4 chunk of r
        float4 v = *(const float4*)(Uw + ((size_t)n * DM + d0 + dl) * RK + q * 4);
        __half2 a = __floats2half2_rn(v.x, v.y);
        __half2 b = __floats2half2_rn(v.z, v.w);
        size_t o = (size_t)(d0 + dl) * DM + n * RK + q * 4;
        *(uint2*)(g_w16 + o) = make_uint2(*(uint32_t*)&a, *(uint32_t*)&b);
        ss += v.x*v.x + v.y*v.y + v.z*v.z + v.w*v.w;
    }
    __shared__ float red[256];
    red[threadIdx.x] = ss;
    __syncthreads();
    for (int off = 128; off > 0; off >>= 1) {
        if (threadIdx.x < off) red[threadIdx.x] += red[threadIdx.x + off];
        __syncthreads();
    }
    if (threadIdx.x == 0) g_upart[blockIdx.x * 16 + blockIdx.y] = red[0];
}

__global__ void frob_kernel(float* __restrict__ frob)
{
    int n = threadIdx.x;  // 64 threads
    float su = 0.0f, sv = 0.0f;
    #pragma unroll
    for (int j = 0; j < 16; j++) su += g_upart[n * 16 + j];
    #pragma unroll
    for (int j = 0; j < 64; j++) sv += g_vpart[n * 64 + j];
    frob[n] = sqrtf(su) * sqrtf(sv) * (1.0f / 256.0f);  // /sqrt(2048*32)
}

// ---------------------------------------------------------------------------
// Warp-MMA GEMM (mma.sync m16n8k16 fp16, fp32 acc), SINGLE pass.
// D[m,n] = sum_k A[m,k]*B[n,k]  (both row-major K-contig)
// Tile: BM=128, BN=128, BK=32. 8 warps (4m x 2n), warp tile 32x64.
// Smem per stage: A(8K) + B(8K) = 16KB, double-buffered = 32KB dyn.
// SW64 swizzle on 64-byte rows: sw = row*64 + (kbyte ^ ((row&6)<<3)).
// MODE 0: A=x, B=Vflat; epilogue *gate -> GVx fp16
// MODE 1: A=GVx, B=Wt;  epilogue fp32 -> out
// ---------------------------------------------------------------------------
#define MMA_SMEM 32768

template<int MODE>
__global__ __launch_bounds__(256) void mma_gemm(const float* __restrict__ gate,
                                                float* __restrict__ outf)
{
    extern __shared__ char sm[];
    const uint32_t sbase = smem_u32(sm);

    const int tid  = threadIdx.x;
    const int wid  = tid >> 5;
    const int lane = tid & 31;
    const int n0 = blockIdx.x * 128;
    const int b0 = blockIdx.y * 128;
    const int wm = (wid & 3) * 32;    // warp m offset
    const int wn = (wid >> 2) * 64;   // warp n offset

    const __half* __restrict__ A16 = (MODE == 0) ? g_x16 : g_gv16;
    const __half* __restrict__ B16 = (MODE == 0) ? g_v16 : g_w16;

    float d[2][8][4];
    #pragma unroll
    for (int i = 0; i < 2; i++)
        #pragma unroll
        for (int j = 0; j < 8; j++)
            #pragma unroll
            for (int r = 0; r < 4; r++) d[i][j][r] = 0.0f;

    // per-thread cp.async coords (2 row-iters x (A,B) of 16B)
    const int r0c = tid >> 2;            // rows 0..63   (it 0)
    const int r1c = 64 + (tid >> 2);     // rows 64..127 (it 1)
    const int cbe = (tid & 3) * 8;       // k-element offset (8 fp16 = 16B)
    const uint32_t sw0 = (uint32_t)r0c * 64 + (((tid & 3) * 16) ^ ((r0c & 6) << 3));
    const uint32_t sw1 = (uint32_t)r1c * 64 + (((tid & 3) * 16) ^ ((r1c & 6) << 3));

    auto issue = [&](int c) {
        const uint32_t st = sbase + (uint32_t)(c & 1) * 16384u;
        const int kb = c * 32;
        const size_t ga0 = (size_t)(b0 + r0c) * DM + kb + cbe;
        const size_t ga1 = (size_t)(b0 + r1c) * DM + kb + cbe;
        const size_t gb0 = (size_t)(n0 + r0c) * DM + kb + cbe;
        const size_t gb1 = (size_t)(n0 + r1c) * DM + kb + cbe;
        cp16(st + sw0,         A16 + ga0);
        cp16(st + sw1,         A16 + ga1);
        cp16(st + 8192 + sw0,  B16 + gb0);
        cp16(st + 8192 + sw1,  B16 + gb1);
        cp_commit();
    };

    // ldmatrix lane address components
    const int a_row = wm + (lane & 15);
    const int a_kc  = (lane >> 4) * 16;
    const int b_row = wn + (lane & 7) + ((lane >> 4) << 3);
    const int b_kc  = ((lane >> 3) & 1) * 16;

    issue(0);

    for (int c = 0; c < 64; ++c) {
        if (c < 63) issue(c + 1);
        if (c < 63) cp_wait<1>(); else cp_wait<0>();
        __syncthreads();

        const uint32_t st = sbase + (uint32_t)(c & 1) * 16384u;

        #pragma unroll
        for (int k16 = 0; k16 < 2; ++k16) {
            const int koff = k16 * 32;  // bytes

            uint32_t bh[4][4];
            #pragma unroll
            for (int q = 0; q < 4; ++q) {
                int row = b_row + q * 16;
                uint32_t sw = (uint32_t)row * 64 +
                              (uint32_t)((koff + b_kc) ^ ((row & 6) << 3));
                ldsm4(bh[q], st + 8192 + sw);
            }
            #pragma unroll
            for (int mb = 0; mb < 2; ++mb) {
                int row = a_row + mb * 16;
                uint32_t sw = (uint32_t)row * 64 +
                              (uint32_t)((koff + a_kc) ^ ((row & 6) << 3));
                uint32_t ah[4];
                ldsm4(ah, st + sw);
                #pragma unroll
                for (int q = 0; q < 4; ++q) {
                    mma_f16(d[mb][q*2],   ah, &bh[q][0]);
                    mma_f16(d[mb][q*2+1], ah, &bh[q][2]);
                }
            }
        }
        __syncthreads();
    }

    // Epilogue. Lane mapping: g = lane>>2 (row within 8), t = lane&3 (col pair)
    const int g = lane >> 2, t = lane & 3;
    #pragma unroll
    for (int mb = 0; mb < 2; ++mb) {
        #pragma unroll
        for (int half = 0; half < 2; ++half) {
            const int b = b0 + wm + mb * 16 + g + half * 8;
            #pragma unroll
            for (int ni = 0; ni < 8; ++ni) {
                const int colg = n0 + wn + ni * 8 + t * 2;
                if (MODE == 0) {
                    const float gv = __ldg(&gate[b * NT + (colg >> 5)]);
                    __half2 h2 = __floats2half2_rn(d[mb][ni][half*2+0] * gv,
                                                   d[mb][ni][half*2+1] * gv);
                    *(uint32_t*)(g_gv16 + (size_t)b * DM + colg) = *(const uint32_t*)&h2;
                } else {
                    *(float2*)(outf + (size_t)b * DM + colg) =
                        make_float2(d[mb][ni][half*2+0], d[mb][ni][half*2+1]);
                }
            }
        }
    }
}

// ---------------------------------------------------------------------------
// d_out layout: [output 2048*2048 | gate 2048*64 | frob 64]
// ---------------------------------------------------------------------------
extern "C" void kernel_launch(void* const* d_in, const int* in_sizes, int n_in,
                              void* d_out, int out_size)
{
    const float* x    = (const float*)d_in[0];  // (2048, 2048)
    const float* Vw   = (const float*)d_in[1];  // (64, 32, 2048)
    const float* Uw   = (const float*)d_in[2];  // (64, 2048, 32)
    const float* enc  = (const float*)d_in[3];  // (64, 2048)
    const float* bias = (const float*)d_in[4];  // (64,)

    float* out  = (float*)d_out;
    float* gate = out + BATCH * DM;
    float* frob = gate + BATCH * NT;

    cudaFuncSetAttribute(mma_gemm<0>, cudaFuncAttributeMaxDynamicSharedMemorySize, MMA_SMEM);
    cudaFuncSetAttribute(mma_gemm<1>, cudaFuncAttributeMaxDynamicSharedMemorySize, MMA_SMEM);

    prep_x<<<(BATCH * DM) / 4 / 256, 256>>>((const float4*)x);
    prep_v<<<(DM * DM) / 4 / 256, 256>>>((const float4*)Vw);
    prep_u<<<dim3(NT, DM / 128), 256>>>(Uw);
    gate_kernel<<<BATCH / 32, 256>>>(x, enc, bias, gate);
    frob_kernel<<<1, NT>>>(frob);

    mma_gemm<0><<<dim3(DM / 128, BATCH / 128), 256, MMA_SMEM>>>(gate, nullptr);
    mma_gemm<1><<<dim3(DM / 128, BATCH / 128), 256, MMA_SMEM>>>(nullptr, out);
}

// round 6
// speedup vs baseline: 3.2059x; 1.3388x over previous
#include <cuda_runtime.h>
#include <cuda_fp16.h>
#include <cstdint>

#define DM 2048   // d_model
#define BATCH 2048
#define NT 64     // num transforms
#define RK 32     // rank

// ---------------------------------------------------------------------------
// Static device scratch (no allocation allowed). Single fp16 operand copies.
// ---------------------------------------------------------------------------
__device__ __half g_x16[BATCH * DM];    // x          [b][d]
__device__ __half g_v16[DM * DM];       // V_flat     [k][d]
__device__ __half g_w16[DM * DM];       // Wt = U^T   [d][k]
__device__ __half g_gv16[BATCH * DM];   // gated Vx   [b][k]
__device__ float g_vpart[4096];         // per-block sum-of-squares partials (V)
__device__ float g_upart[1024];         // per-block partials (U): [n*16 + dblk]
__device__ float g_gpart8[8 * BATCH * NT];  // gate split-K partials (4 MB)

// ---------------------------------------------------------------------------
// PTX helpers (portable sm_80 subset; ptxas here targets plain sm_103)
// ---------------------------------------------------------------------------
__device__ __forceinline__ uint32_t smem_u32(const void* p) {
    return (uint32_t)__cvta_generic_to_shared(p);
}
__device__ __forceinline__ void cp16(uint32_t dst, const void* src) {
    asm volatile("cp.async.cg.shared.global [%0], [%1], 16;\n" :: "r"(dst), "l"(src));
}
__device__ __forceinline__ void cp_commit() {
    asm volatile("cp.async.commit_group;\n" ::: "memory");
}
template<int N>
__device__ __forceinline__ void cp_wait() {
    asm volatile("cp.async.wait_group %0;\n" :: "n"(N) : "memory");
}
__device__ __forceinline__ void ldsm4(uint32_t* r, uint32_t addr) {
    asm volatile("ldmatrix.sync.aligned.m8n8.x4.shared.b16 {%0,%1,%2,%3}, [%4];"
                 : "=r"(r[0]), "=r"(r[1]), "=r"(r[2]), "=r"(r[3]) : "r"(addr));
}
__device__ __forceinline__ void mma_f16(float* d, const uint32_t* a, const uint32_t* b) {
    asm volatile(
        "mma.sync.aligned.m16n8k16.row.col.f32.f16.f16.f32 "
        "{%0,%1,%2,%3}, {%4,%5,%6,%7}, {%8,%9}, {%0,%1,%2,%3};"
        : "+f"(d[0]), "+f"(d[1]), "+f"(d[2]), "+f"(d[3])
        : "r"(a[0]), "r"(a[1]), "r"(a[2]), "r"(a[3]), "r"(b[0]), "r"(b[1]));
}

// ---------------------------------------------------------------------------
// Gate phase A: split-K partials. grid (8 kc, 64 bt), K-chunk = 256.
// Same tile math as the proven R3 gate kernel, restricted to one k-chunk.
// ---------------------------------------------------------------------------
__global__ __launch_bounds__(256) void gate_partial(
    const float* __restrict__ x, const float* __restrict__ enc)
{
    __shared__ __align__(16) float As[32][36];
    __shared__ __align__(16) float Es[32][68];

    const int tid = threadIdx.x;
    const int tx = tid & 15, ty = tid >> 4;
    const int kb = blockIdx.x * 256;
    const int b0 = blockIdx.y * 32;
    const int f4 = tid & 7, lrow = tid >> 3;

    float acc[2][4];
    #pragma unroll
    for (int i = 0; i < 2; i++)
        #pragma unroll
        for (int j = 0; j < 4; j++) acc[i][j] = 0.0f;

    for (int d0 = kb; d0 < kb + 256; d0 += 32) {
        {
            float4 v = *(const float4*)(x + (size_t)(b0 + lrow) * DM + d0 + f4 * 4);
            As[f4*4+0][lrow] = v.x; As[f4*4+1][lrow] = v.y;
            As[f4*4+2][lrow] = v.z; As[f4*4+3][lrow] = v.w;
        }
        #pragma unroll
        for (int p = 0; p < 2; p++) {
            int row = p * 32 + lrow;
            float4 v = *(const float4*)(enc + (size_t)row * DM + d0 + f4 * 4);
            Es[f4*4+0][row] = v.x; Es[f4*4+1][row] = v.y;
            Es[f4*4+2][row] = v.z; Es[f4*4+3][row] = v.w;
        }
        __syncthreads();
        #pragma unroll
        for (int kk = 0; kk < 32; kk++) {
            float a0 = As[kk][ty*2 + 0];
            float a1 = As[kk][ty*2 + 1];
            float4 e = *(const float4*)&Es[kk][tx*4];
            acc[0][0] += a0 * e.x; acc[0][1] += a0 * e.y;
            acc[0][2] += a0 * e.z; acc[0][3] += a0 * e.w;
            acc[1][0] += a1 * e.x; acc[1][1] += a1 * e.y;
            acc[1][2] += a1 * e.z; acc[1][3] += a1 * e.w;
        }
        __syncthreads();
    }
    float* dst = g_gpart8 + (size_t)blockIdx.x * (BATCH * NT);
    #pragma unroll
    for (int i = 0; i < 2; i++) {
        int b = b0 + ty*2 + i;
        #pragma unroll
        for (int j = 0; j < 4; j++)
            dst[b * NT + tx*4 + j] = acc[i][j];
    }
}

// Gate phase B: deterministic reduction over 8 chunks + bias + relu.
__global__ __launch_bounds__(256) void gate_reduce(
    const float* __restrict__ bias, float* __restrict__ gate)
{
    int idx = blockIdx.x * 256 + threadIdx.x;   // 0 .. 131071
    int n = idx & (NT - 1);
    float s = 0.0f;
    #pragma unroll
    for (int c = 0; c < 8; ++c) s += g_gpart8[(size_t)c * (BATCH * NT) + idx];
    float p = s - bias[n];
    gate[idx] = (p > 0.0f) ? p : 0.0f;
}

// ---------------------------------------------------------------------------
// Prep kernels: fp32 -> fp16, norms fused where the data is already in flight
// ---------------------------------------------------------------------------
__global__ __launch_bounds__(256) void prep_x(const float4* __restrict__ src)
{
    int i = blockIdx.x * 256 + threadIdx.x;
    float4 v = src[i];
    __half2 a = __floats2half2_rn(v.x, v.y);
    __half2 b = __floats2half2_rn(v.z, v.w);
    ((uint2*)g_x16)[i] = make_uint2(*(uint32_t*)&a, *(uint32_t*)&b);
}

__global__ __launch_bounds__(256) void prep_v(const float4* __restrict__ src)
{
    int i = blockIdx.x * 256 + threadIdx.x;
    float4 v = src[i];
    __half2 a = __floats2half2_rn(v.x, v.y);
    __half2 b = __floats2half2_rn(v.z, v.w);
    ((uint2*)g_v16)[i] = make_uint2(*(uint32_t*)&a, *(uint32_t*)&b);

    float s = v.x*v.x + v.y*v.y + v.z*v.z + v.w*v.w;
    __shared__ float red[256];
    red[threadIdx.x] = s;
    __syncthreads();
    for (int off = 128; off > 0; off >>= 1) {
        if (threadIdx.x < off) red[threadIdx.x] += red[threadIdx.x + off];
        __syncthreads();
    }
    if (threadIdx.x == 0) g_vpart[blockIdx.x] = red[0];
}

__global__ __launch_bounds__(256) void prep_u(const float* __restrict__ Uw)
{
    const int n  = blockIdx.x;        // 0..63
    const int d0 = blockIdx.y * 128;  // 16 blocks
    float ss = 0.0f;
    #pragma unroll
    for (int it = 0; it < 4; it++) {
        int lin = threadIdx.x + it * 256;   // 0..1023
        int dl = lin >> 3;                  // 0..127
        int q  = lin & 7;                   // float4 chunk of r
        float4 v = *(const float4*)(Uw + ((size_t)n * DM + d0 + dl) * RK + q * 4);
        __half2 a = __floats2half2_rn(v.x, v.y);
        __half2 b = __floats2half2_rn(v.z, v.w);
        size_t o = (size_t)(d0 + dl) * DM + n * RK + q * 4;
        *(uint2*)(g_w16 + o) = make_uint2(*(uint32_t*)&a, *(uint32_t*)&b);
        ss += v.x*v.x + v.y*v.y + v.z*v.z + v.w*v.w;
    }
    __shared__ float red[256];
    red[threadIdx.x] = ss;
    __syncthreads();
    for (int off = 128; off > 0; off >>= 1) {
        if (threadIdx.x < off) red[threadIdx.x] += red[threadIdx.x + off];
        __syncthreads();
    }
    if (threadIdx.x == 0) g_upart[blockIdx.x * 16 + blockIdx.y] = red[0];
}

__global__ void frob_kernel(float* __restrict__ frob)
{
    int n = threadIdx.x;  // 64 threads
    float su = 0.0f, sv = 0.0f;
    #pragma unroll
    for (int j = 0; j < 16; j++) su += g_upart[n * 16 + j];
    #pragma unroll
    for (int j = 0; j < 64; j++) sv += g_vpart[n * 64 + j];
    frob[n] = sqrtf(su) * sqrtf(sv) * (1.0f / 256.0f);  // /sqrt(2048*32)
}

// ---------------------------------------------------------------------------
// Warp-MMA GEMM (mma.sync m16n8k16 fp16, fp32 acc), SINGLE pass.
// D[m,n] = sum_k A[m,k]*B[n,k]  (both row-major K-contig)
// Tile: BM=128, BN=128, BK=32. 8 warps (4m x 2n), warp tile 32x64.
// Smem per stage: A(8K) + B(8K) = 16KB, double-buffered = 32KB dyn.
// SW64 swizzle on 64-byte rows: sw = row*64 + (kbyte ^ ((row&6)<<3)).
// MODE 0: A=x, B=Vflat; epilogue *gate -> GVx fp16
// MODE 1: A=GVx, B=Wt;  epilogue fp32 -> out
// ---------------------------------------------------------------------------
#define MMA_SMEM 32768

template<int MODE>
__global__ __launch_bounds__(256) void mma_gemm(const float* __restrict__ gate,
                                                float* __restrict__ outf)
{
    extern __shared__ char sm[];
    const uint32_t sbase = smem_u32(sm);

    const int tid  = threadIdx.x;
    const int wid  = tid >> 5;
    const int lane = tid & 31;
    const int n0 = blockIdx.x * 128;
    const int b0 = blockIdx.y * 128;
    const int wm = (wid & 3) * 32;    // warp m offset
    const int wn = (wid >> 2) * 64;   // warp n offset

    const __half* __restrict__ A16 = (MODE == 0) ? g_x16 : g_gv16;
    const __half* __restrict__ B16 = (MODE == 0) ? g_v16 : g_w16;

    float d[2][8][4];
    #pragma unroll
    for (int i = 0; i < 2; i++)
        #pragma unroll
        for (int j = 0; j < 8; j++)
            #pragma unroll
            for (int r = 0; r < 4; r++) d[i][j][r] = 0.0f;

    // per-thread cp.async coords (2 row-iters x (A,B) of 16B)
    const int r0c = tid >> 2;            // rows 0..63   (it 0)
    const int r1c = 64 + (tid >> 2);     // rows 64..127 (it 1)
    const int cbe = (tid & 3) * 8;       // k-element offset (8 fp16 = 16B)
    const uint32_t sw0 = (uint32_t)r0c * 64 + (((tid & 3) * 16) ^ ((r0c & 6) << 3));
    const uint32_t sw1 = (uint32_t)r1c * 64 + (((tid & 3) * 16) ^ ((r1c & 6) << 3));

    auto issue = [&](int c) {
        const uint32_t st = sbase + (uint32_t)(c & 1) * 16384u;
        const int kb = c * 32;
        const size_t ga0 = (size_t)(b0 + r0c) * DM + kb + cbe;
        const size_t ga1 = (size_t)(b0 + r1c) * DM + kb + cbe;
        const size_t gb0 = (size_t)(n0 + r0c) * DM + kb + cbe;
        const size_t gb1 = (size_t)(n0 + r1c) * DM + kb + cbe;
        cp16(st + sw0,         A16 + ga0);
        cp16(st + sw1,         A16 + ga1);
        cp16(st + 8192 + sw0,  B16 + gb0);
        cp16(st + 8192 + sw1,  B16 + gb1);
        cp_commit();
    };

    // ldmatrix lane address components
    const int a_row = wm + (lane & 15);
    const int a_kc  = (lane >> 4) * 16;
    const int b_row = wn + (lane & 7) + ((lane >> 4) << 3);
    const int b_kc  = ((lane >> 3) & 1) * 16;

    issue(0);

    for (int c = 0; c < 64; ++c) {
        if (c < 63) issue(c + 1);
        if (c < 63) cp_wait<1>(); else cp_wait<0>();
        __syncthreads();

        const uint32_t st = sbase + (uint32_t)(c & 1) * 16384u;

        #pragma unroll
        for (int k16 = 0; k16 < 2; ++k16) {
            const int koff = k16 * 32;  // bytes

            uint32_t bh[4][4];
            #pragma unroll
            for (int q = 0; q < 4; ++q) {
                int row = b_row + q * 16;
                uint32_t sw = (uint32_t)row * 64 +
                              (uint32_t)((koff + b_kc) ^ ((row & 6) << 3));
                ldsm4(bh[q], st + 8192 + sw);
            }
            #pragma unroll
            for (int mb = 0; mb < 2; ++mb) {
                int row = a_row + mb * 16;
                uint32_t sw = (uint32_t)row * 64 +
                              (uint32_t)((koff + a_kc) ^ ((row & 6) << 3));
                uint32_t ah[4];
                ldsm4(ah, st + sw);
                #pragma unroll
                for (int q = 0; q < 4; ++q) {
                    mma_f16(d[mb][q*2],   ah, &bh[q][0]);
                    mma_f16(d[mb][q*2+1], ah, &bh[q][2]);
                }
            }
        }
        __syncthreads();
    }

    // Epilogue. Lane mapping: g = lane>>2 (row within 8), t = lane&3 (col pair)
    const int g = lane >> 2, t = lane & 3;
    #pragma unroll
    for (int mb = 0; mb < 2; ++mb) {
        #pragma unroll
        for (int half = 0; half < 2; ++half) {
            const int b = b0 + wm + mb * 16 + g + half * 8;
            #pragma unroll
            for (int ni = 0; ni < 8; ++ni) {
                const int colg = n0 + wn + ni * 8 + t * 2;
                if (MODE == 0) {
                    const float gv = __ldg(&gate[b * NT + (colg >> 5)]);
                    __half2 h2 = __floats2half2_rn(d[mb][ni][half*2+0] * gv,
                                                   d[mb][ni][half*2+1] * gv);
                    *(uint32_t*)(g_gv16 + (size_t)b * DM + colg) = *(const uint32_t*)&h2;
                } else {
                    *(float2*)(outf + (size_t)b * DM + colg) =
                        make_float2(d[mb][ni][half*2+0], d[mb][ni][half*2+1]);
                }
            }
        }
    }
}

// ---------------------------------------------------------------------------
// d_out layout: [output 2048*2048 | gate 2048*64 | frob 64]
// ---------------------------------------------------------------------------
extern "C" void kernel_launch(void* const* d_in, const int* in_sizes, int n_in,
                              void* d_out, int out_size)
{
    const float* x    = (const float*)d_in[0];  // (2048, 2048)
    const float* Vw   = (const float*)d_in[1];  // (64, 32, 2048)
    const float* Uw   = (const float*)d_in[2];  // (64, 2048, 32)
    const float* enc  = (const float*)d_in[3];  // (64, 2048)
    const float* bias = (const float*)d_in[4];  // (64,)

    float* out  = (float*)d_out;
    float* gate = out + BATCH * DM;
    float* frob = gate + BATCH * NT;

    cudaFuncSetAttribute(mma_gemm<0>, cudaFuncAttributeMaxDynamicSharedMemorySize, MMA_SMEM);
    cudaFuncSetAttribute(mma_gemm<1>, cudaFuncAttributeMaxDynamicSharedMemorySize, MMA_SMEM);

    gate_partial<<<dim3(8, BATCH / 32), 256>>>(x, enc);
    prep_x<<<(BATCH * DM) / 4 / 256, 256>>>((const float4*)x);
    prep_v<<<(DM * DM) / 4 / 256, 256>>>((const float4*)Vw);
    prep_u<<<dim3(NT, DM / 128), 256>>>(Uw);
    gate_reduce<<<(BATCH * NT) / 256, 256>>>(bias, gate);
    frob_kernel<<<1, NT>>>(frob);

    mma_gemm<0><<<dim3(DM / 128, BATCH / 128), 256, MMA_SMEM>>>(gate, nullptr);
    mma_gemm<1><<<dim3(DM / 128, BATCH / 128), 256, MMA_SMEM>>>(nullptr, out);
}

// round 7
// speedup vs baseline: 3.7458x; 1.1684x over previous
#include <cuda_runtime.h>
#include <cuda_fp16.h>
#include <cstdint>

#define DM 2048   // d_model
#define BATCH 2048
#define NT 64     // num transforms
#define RK 32     // rank

// ---------------------------------------------------------------------------
// Static device scratch (no allocation allowed). Single fp16 operand copies.
// ---------------------------------------------------------------------------
__device__ __half g_x16[BATCH * DM];    // x          [b][d]
__device__ __half g_e16[NT * DM];       // encoder    [n][d]
__device__ __half g_v16[DM * DM];       // V_flat     [k][d]
__device__ __half g_w16[DM * DM];       // Wt = U^T   [d][k]
__device__ __half g_gv16[BATCH * DM];   // gated Vx   [b][k]
__device__ float g_vpart[4096];         // per-block sum-of-squares partials (V)
__device__ float g_upart[1024];         // per-block partials (U): [n*16 + dblk]
__device__ float g_gpart8[8 * BATCH * NT];  // gate split-K partials (4 MB)

// ---------------------------------------------------------------------------
// PTX helpers (portable sm_80 subset; ptxas here targets plain sm_103)
// ---------------------------------------------------------------------------
__device__ __forceinline__ uint32_t smem_u32(const void* p) {
    return (uint32_t)__cvta_generic_to_shared(p);
}
__device__ __forceinline__ void cp16(uint32_t dst, const void* src) {
    asm volatile("cp.async.cg.shared.global [%0], [%1], 16;\n" :: "r"(dst), "l"(src));
}
__device__ __forceinline__ void cp_commit() {
    asm volatile("cp.async.commit_group;\n" ::: "memory");
}
template<int N>
__device__ __forceinline__ void cp_wait() {
    asm volatile("cp.async.wait_group %0;\n" :: "n"(N) : "memory");
}
__device__ __forceinline__ void ldsm4(uint32_t* r, uint32_t addr) {
    asm volatile("ldmatrix.sync.aligned.m8n8.x4.shared.b16 {%0,%1,%2,%3}, [%4];"
                 : "=r"(r[0]), "=r"(r[1]), "=r"(r[2]), "=r"(r[3]) : "r"(addr));
}
__device__ __forceinline__ void mma_f16(float* d, const uint32_t* a, const uint32_t* b) {
    asm volatile(
        "mma.sync.aligned.m16n8k16.row.col.f32.f16.f16.f32 "
        "{%0,%1,%2,%3}, {%4,%5,%6,%7}, {%8,%9}, {%0,%1,%2,%3};"
        : "+f"(d[0]), "+f"(d[1]), "+f"(d[2]), "+f"(d[3])
        : "r"(a[0]), "r"(a[1]), "r"(a[2]), "r"(a[3]), "r"(b[0]), "r"(b[1]));
}

// ---------------------------------------------------------------------------
// Prep kernels: fp32 -> fp16, norms fused where the data is already in flight
// ---------------------------------------------------------------------------
__global__ __launch_bounds__(256) void prep_x(const float4* __restrict__ src)
{
    int i = blockIdx.x * 256 + threadIdx.x;
    float4 v = src[i];
    __half2 a = __floats2half2_rn(v.x, v.y);
    __half2 b = __floats2half2_rn(v.z, v.w);
    ((uint2*)g_x16)[i] = make_uint2(*(uint32_t*)&a, *(uint32_t*)&b);
}

__global__ __launch_bounds__(256) void prep_enc(const float4* __restrict__ src)
{
    int i = blockIdx.x * 256 + threadIdx.x;   // over 32768 float4s
    float4 v = src[i];
    __half2 a = __floats2half2_rn(v.x, v.y);
    __half2 b = __floats2half2_rn(v.z, v.w);
    ((uint2*)g_e16)[i] = make_uint2(*(uint32_t*)&a, *(uint32_t*)&b);
}

__global__ __launch_bounds__(256) void prep_v(const float4* __restrict__ src)
{
    int i = blockIdx.x * 256 + threadIdx.x;
    float4 v = src[i];
    __half2 a = __floats2half2_rn(v.x, v.y);
    __half2 b = __floats2half2_rn(v.z, v.w);
    ((uint2*)g_v16)[i] = make_uint2(*(uint32_t*)&a, *(uint32_t*)&b);

    float s = v.x*v.x + v.y*v.y + v.z*v.z + v.w*v.w;
    __shared__ float red[256];
    red[threadIdx.x] = s;
    __syncthreads();
    for (int off = 128; off > 0; off >>= 1) {
        if (threadIdx.x < off) red[threadIdx.x] += red[threadIdx.x + off];
        __syncthreads();
    }
    if (threadIdx.x == 0) g_vpart[blockIdx.x] = red[0];
}

__global__ __launch_bounds__(256) void prep_u(const float* __restrict__ Uw)
{
    const int n  = blockIdx.x;        // 0..63
    const int d0 = blockIdx.y * 128;  // 16 blocks
    float ss = 0.0f;
    #pragma unroll
    for (int it = 0; it < 4; it++) {
        int lin = threadIdx.x + it * 256;   // 0..1023
        int dl = lin >> 3;                  // 0..127
        int q  = lin & 7;                   // float4 chunk of r
        float4 v = *(const float4*)(Uw + ((size_t)n * DM + d0 + dl) * RK + q * 4);
        __half2 a = __floats2half2_rn(v.x, v.y);
        __half2 b = __floats2half2_rn(v.z, v.w);
        size_t o = (size_t)(d0 + dl) * DM + n * RK + q * 4;
        *(uint2*)(g_w16 + o) = make_uint2(*(uint32_t*)&a, *(uint32_t*)&b);
        ss += v.x*v.x + v.y*v.y + v.z*v.z + v.w*v.w;
    }
    __shared__ float red[256];
    red[threadIdx.x] = ss;
    __syncthreads();
    for (int off = 128; off > 0; off >>= 1) {
        if (threadIdx.x < off) red[threadIdx.x] += red[threadIdx.x + off];
        __syncthreads();
    }
    if (threadIdx.x == 0) g_upart[blockIdx.x * 16 + blockIdx.y] = red[0];
}

__global__ void frob_kernel(float* __restrict__ frob)
{
    int n = threadIdx.x;  // 64 threads
    float su = 0.0f, sv = 0.0f;
    #pragma unroll
    for (int j = 0; j < 16; j++) su += g_upart[n * 16 + j];
    #pragma unroll
    for (int j = 0; j < 64; j++) sv += g_vpart[n * 64 + j];
    frob[n] = sqrtf(su) * sqrtf(sv) * (1.0f / 256.0f);  // /sqrt(2048*32)
}

// ---------------------------------------------------------------------------
// Gate phase A (tensor pipe): partial[kc][b][n] = sum_{k in chunk} x16[b,k]*e16[n,k]
// BM=128, BN=64, Kchunk=256 (8 k-tiles of 32). grid (8 kc, 16 mb) = 128 CTAs.
// 8 warps: 4m x 2n, warp tile 32x32. Double-buffered cp.async, SW64 swizzle.
// ---------------------------------------------------------------------------
__global__ __launch_bounds__(256) void gate_mma(void)
{
    __shared__ __align__(1024) char sm[2 * 12288];   // stage: A 8K | B 4K
    const uint32_t sbase = smem_u32(sm);

    const int tid  = threadIdx.x;
    const int wid  = tid >> 5;
    const int lane = tid & 31;
    const int kb = blockIdx.x * 256;
    const int b0 = blockIdx.y * 128;
    const int wm = (wid & 3) * 32;
    const int wn = (wid >> 2) * 32;

    float d[2][4][4];
    #pragma unroll
    for (int i = 0; i < 2; i++)
        #pragma unroll
        for (int j = 0; j < 4; j++)
            #pragma unroll
            for (int r = 0; r < 4; r++) d[i][j][r] = 0.0f;

    const int rA = tid >> 2;              // 0..63 (+64 second iter)
    const int cbe = (tid & 3) * 8;        // k-element offset (8 fp16 = 16B)
    const uint32_t swA0 = (uint32_t)rA * 64 + (((tid & 3) * 16) ^ ((rA & 6) << 3));
    const int rA1 = rA + 64;
    const uint32_t swA1 = (uint32_t)rA1 * 64 + (((tid & 3) * 16) ^ ((rA1 & 6) << 3));

    auto issue = [&](int c) {
        const uint32_t st = sbase + (uint32_t)(c & 1) * 12288u;
        const int k0 = kb + c * 32;
        cp16(st + swA0,        g_x16 + (size_t)(b0 + rA) * DM + k0 + cbe);
        cp16(st + swA1,        g_x16 + (size_t)(b0 + rA1) * DM + k0 + cbe);
        // B (enc): 64 rows x 64B = exactly 256 chunks
        cp16(st + 8192 + swA0, g_e16 + (size_t)rA * DM + k0 + cbe);
        cp_commit();
    };

    const int a_row = wm + (lane & 15);
    const int a_kc  = (lane >> 4) * 16;
    const int b_row = wn + (lane & 7) + ((lane >> 4) << 3);
    const int b_kc  = ((lane >> 3) & 1) * 16;

    issue(0);

    for (int c = 0; c < 8; ++c) {
        if (c < 7) issue(c + 1);
        if (c < 7) cp_wait<1>(); else cp_wait<0>();
        __syncthreads();

        const uint32_t st = sbase + (uint32_t)(c & 1) * 12288u;

        #pragma unroll
        for (int k16 = 0; k16 < 2; ++k16) {
            const int koff = k16 * 32;
            uint32_t bh[2][4];
            #pragma unroll
            for (int q = 0; q < 2; ++q) {
                int row = b_row + q * 16;
                uint32_t sw = (uint32_t)row * 64 +
                              (uint32_t)((koff + b_kc) ^ ((row & 6) << 3));
                ldsm4(bh[q], st + 8192 + sw);
            }
            #pragma unroll
            for (int mb = 0; mb < 2; ++mb) {
                int row = a_row + mb * 16;
                uint32_t sw = (uint32_t)row * 64 +
                              (uint32_t)((koff + a_kc) ^ ((row & 6) << 3));
                uint32_t ah[4];
                ldsm4(ah, st + sw);
                #pragma unroll
                for (int q = 0; q < 2; ++q) {
                    mma_f16(d[mb][q*2],   ah, &bh[q][0]);
                    mma_f16(d[mb][q*2+1], ah, &bh[q][2]);
                }
            }
        }
        __syncthreads();
    }

    float* dst = g_gpart8 + (size_t)blockIdx.x * (BATCH * NT);
    const int g = lane >> 2, t = lane & 3;
    #pragma unroll
    for (int mb = 0; mb < 2; ++mb) {
        #pragma unroll
        for (int half = 0; half < 2; ++half) {
            const int b = b0 + wm + mb * 16 + g + half * 8;
            #pragma unroll
            for (int nf = 0; nf < 4; ++nf) {
                const int col = wn + nf * 8 + t * 2;
                *(float2*)(dst + b * NT + col) =
                    make_float2(d[mb][nf][half*2+0], d[mb][nf][half*2+1]);
            }
        }
    }
}

// Gate phase B: deterministic reduction over 8 chunks + bias + relu.
__global__ __launch_bounds__(256) void gate_reduce(
    const float* __restrict__ bias, float* __restrict__ gate)
{
    int idx = blockIdx.x * 256 + threadIdx.x;   // 0 .. 131071
    int n = idx & (NT - 1);
    float s = 0.0f;
    #pragma unroll
    for (int c = 0; c < 8; ++c) s += g_gpart8[(size_t)c * (BATCH * NT) + idx];
    float p = s - bias[n];
    gate[idx] = (p > 0.0f) ? p : 0.0f;
}

// ---------------------------------------------------------------------------
// Warp-MMA GEMM (mma.sync m16n8k16 fp16, fp32 acc), SINGLE pass.
// D[m,n] = sum_k A[m,k]*B[n,k]  (both row-major K-contig)
// Tile: BM=128, BN=128, BK=32. 8 warps (4m x 2n), warp tile 32x64.
// Smem per stage: A(8K) + B(8K) = 16KB, double-buffered = 32KB dyn.
// SW64 swizzle on 64-byte rows: sw = row*64 + (kbyte ^ ((row&6)<<3)).
// MODE 0: A=x, B=Vflat; epilogue *gate -> GVx fp16
// MODE 1: A=GVx, B=Wt;  epilogue fp32 -> out
// ---------------------------------------------------------------------------
#define MMA_SMEM 32768

template<int MODE>
__global__ __launch_bounds__(256) void mma_gemm(const float* __restrict__ gate,
                                                float* __restrict__ outf)
{
    extern __shared__ char sm[];
    const uint32_t sbase = smem_u32(sm);

    const int tid  = threadIdx.x;
    const int wid  = tid >> 5;
    const int lane = tid & 31;
    const int n0 = blockIdx.x * 128;
    const int b0 = blockIdx.y * 128;
    const int wm = (wid & 3) * 32;    // warp m offset
    const int wn = (wid >> 2) * 64;   // warp n offset

    const __half* __restrict__ A16 = (MODE == 0) ? g_x16 : g_gv16;
    const __half* __restrict__ B16 = (MODE == 0) ? g_v16 : g_w16;

    float d[2][8][4];
    #pragma unroll
    for (int i = 0; i < 2; i++)
        #pragma unroll
        for (int j = 0; j < 8; j++)
            #pragma unroll
            for (int r = 0; r < 4; r++) d[i][j][r] = 0.0f;

    // per-thread cp.async coords (2 row-iters x (A,B) of 16B)
    const int r0c = tid >> 2;            // rows 0..63   (it 0)
    const int r1c = 64 + (tid >> 2);     // rows 64..127 (it 1)
    const int cbe = (tid & 3) * 8;       // k-element offset (8 fp16 = 16B)
    const uint32_t sw0 = (uint32_t)r0c * 64 + (((tid & 3) * 16) ^ ((r0c & 6) << 3));
    const uint32_t sw1 = (uint32_t)r1c * 64 + (((tid & 3) * 16) ^ ((r1c & 6) << 3));

    auto issue = [&](int c) {
        const uint32_t st = sbase + (uint32_t)(c & 1) * 16384u;
        const int kb = c * 32;
        const size_t ga0 = (size_t)(b0 + r0c) * DM + kb + cbe;
        const size_t ga1 = (size_t)(b0 + r1c) * DM + kb + cbe;
        const size_t gb0 = (size_t)(n0 + r0c) * DM + kb + cbe;
        const size_t gb1 = (size_t)(n0 + r1c) * DM + kb + cbe;
        cp16(st + sw0,         A16 + ga0);
        cp16(st + sw1,         A16 + ga1);
        cp16(st + 8192 + sw0,  B16 + gb0);
        cp16(st + 8192 + sw1,  B16 + gb1);
        cp_commit();
    };

    // ldmatrix lane address components
    const int a_row = wm + (lane & 15);
    const int a_kc  = (lane >> 4) * 16;
    const int b_row = wn + (lane & 7) + ((lane >> 4) << 3);
    const int b_kc  = ((lane >> 3) & 1) * 16;

    issue(0);

    for (int c = 0; c < 64; ++c) {
        if (c < 63) issue(c + 1);
        if (c < 63) cp_wait<1>(); else cp_wait<0>();
        __syncthreads();

        const uint32_t st = sbase + (uint32_t)(c & 1) * 16384u;

        #pragma unroll
        for (int k16 = 0; k16 < 2; ++k16) {
            const int koff = k16 * 32;  // bytes

            uint32_t bh[4][4];
            #pragma unroll
            for (int q = 0; q < 4; ++q) {
                int row = b_row + q * 16;
                uint32_t sw = (uint32_t)row * 64 +
                              (uint32_t)((koff + b_kc) ^ ((row & 6) << 3));
                ldsm4(bh[q], st + 8192 + sw);
            }
            #pragma unroll
            for (int mb = 0; mb < 2; ++mb) {
                int row = a_row + mb * 16;
                uint32_t sw = (uint32_t)row * 64 +
                              (uint32_t)((koff + a_kc) ^ ((row & 6) << 3));
                uint32_t ah[4];
                ldsm4(ah, st + sw);
                #pragma unroll
                for (int q = 0; q < 4; ++q) {
                    mma_f16(d[mb][q*2],   ah, &bh[q][0]);
                    mma_f16(d[mb][q*2+1], ah, &bh[q][2]);
                }
            }
        }
        __syncthreads();
    }

    // Epilogue. Lane mapping: g = lane>>2 (row within 8), t = lane&3 (col pair)
    const int g = lane >> 2, t = lane & 3;
    #pragma unroll
    for (int mb = 0; mb < 2; ++mb) {
        #pragma unroll
        for (int half = 0; half < 2; ++half) {
            const int b = b0 + wm + mb * 16 + g + half * 8;
            #pragma unroll
            for (int ni = 0; ni < 8; ++ni) {
                const int colg = n0 + wn + ni * 8 + t * 2;
                if (MODE == 0) {
                    const float gv = __ldg(&gate[b * NT + (colg >> 5)]);
                    __half2 h2 = __floats2half2_rn(d[mb][ni][half*2+0] * gv,
                                                   d[mb][ni][half*2+1] * gv);
                    *(uint32_t*)(g_gv16 + (size_t)b * DM + colg) = *(const uint32_t*)&h2;
                } else {
                    *(float2*)(outf + (size_t)b * DM + colg) =
                        make_float2(d[mb][ni][half*2+0], d[mb][ni][half*2+1]);
                }
            }
        }
    }
}

// ---------------------------------------------------------------------------
// d_out layout: [output 2048*2048 | gate 2048*64 | frob 64]
// ---------------------------------------------------------------------------
extern "C" void kernel_launch(void* const* d_in, const int* in_sizes, int n_in,
                              void* d_out, int out_size)
{
    const float* x    = (const float*)d_in[0];  // (2048, 2048)
    const float* Vw   = (const float*)d_in[1];  // (64, 32, 2048)
    const float* Uw   = (const float*)d_in[2];  // (64, 2048, 32)
    const float* enc  = (const float*)d_in[3];  // (64, 2048)
    const float* bias = (const float*)d_in[4];  // (64,)

    float* out  = (float*)d_out;
    float* gate = out + BATCH * DM;
    float* frob = gate + BATCH * NT;

    cudaFuncSetAttribute(mma_gemm<0>, cudaFuncAttributeMaxDynamicSharedMemorySize, MMA_SMEM);
    cudaFuncSetAttribute(mma_gemm<1>, cudaFuncAttributeMaxDynamicSharedMemorySize, MMA_SMEM);

    prep_x<<<(BATCH * DM) / 4 / 256, 256>>>((const float4*)x);
    prep_enc<<<(NT * DM) / 4 / 256, 256>>>((const float4*)enc);
    prep_v<<<(DM * DM) / 4 / 256, 256>>>((const float4*)Vw);
    prep_u<<<dim3(NT, DM / 128), 256>>>(Uw);
    gate_mma<<<dim3(8, BATCH / 128), 256>>>();
    gate_reduce<<<(BATCH * NT) / 256, 256>>>(bias, gate);
    frob_kernel<<<1, NT>>>(frob);

    mma_gemm<0><<<dim3(DM / 128, BATCH / 128), 256, MMA_SMEM>>>(gate, nullptr);
    mma_gemm<1><<<dim3(DM / 128, BATCH / 128), 256, MMA_SMEM>>>(nullptr, out);
}